// round 14
// baseline (speedup 1.0000x reference)
#include <cuda_runtime.h>
#include <cstdint>

typedef unsigned long long ull;

#define BB    8192
#define LL    128
#define OO    512
#define KK    8
#define HH    20

#define OTILE   4      // o's per block, one per warp (128 threads)
#define BTILE   256    // b's per block (2 passes x 4 per thread x 32 lanes)
#define BPP     4      // b's per pass per thread

#define WSTRIDE 644
#define WFLOATS (OTILE * WSTRIDE)
#define NPAD    5      // nsm/osm row stride (floats): odd -> conflict-free column reads

__device__ float g_xT[LL * BB];        //  4 MB : xT[l][b]

static __device__ __forceinline__ ull pack2(float lo, float hi) {
    ull r; asm("mov.b64 %0, {%1, %2};" : "=l"(r) : "f"(lo), "f"(hi)); return r;
}
static __device__ __forceinline__ float2 unpack2(ull v) {
    float2 f; asm("mov.b64 {%0, %1}, %2;" : "=f"(f.x), "=f"(f.y) : "l"(v)); return f;
}
static __device__ __forceinline__ ull dup2(float v) {
    ull r; asm("mov.b64 %0, {%1, %1};" : "=l"(r) : "f"(v)); return r;
}
static __device__ __forceinline__ ull fma2(ull a, ull b, ull c) {
    ull d; asm("fma.rn.f32x2 %0, %1, %2, %3;" : "=l"(d) : "l"(a), "l"(b), "l"(c)); return d;
}
static __device__ __forceinline__ float tanh_f(float x) {
    float r; asm("tanh.approx.f32 %0, %1;" : "=f"(r) : "f"(x)); return r;
}
static __device__ __forceinline__ ull tanh2(ull v) {
    float2 f = unpack2(v);
    return pack2(tanh_f(f.x), tanh_f(f.y));
}

__global__ void __launch_bounds__(256)
transpose_k(const float* __restrict__ src, float* __restrict__ dst,
            int rows, int cols)
{
    __shared__ float tile[32][33];
    int c  = blockIdx.x * 32 + threadIdx.x;
    int r0 = blockIdx.y * 32;
#pragma unroll
    for (int j = 0; j < 32; j += 8)
        tile[threadIdx.y + j][threadIdx.x] =
            src[(size_t)(r0 + threadIdx.y + j) * cols + c];
    __syncthreads();
    int r  = r0 + threadIdx.x;
    int c0 = blockIdx.x * 32 + threadIdx.y;
#pragma unroll
    for (int j = 0; j < 32; j += 8)
        dst[(size_t)(c0 + j) * rows + r] = tile[threadIdx.x][threadIdx.y + j];
}

__global__ void __launch_bounds__(128, 4)
medil_kernel(const float* __restrict__ noise,
             const int*   __restrict__ cause,
             const float* __restrict__ W1,
             const float* __restrict__ b1,
             const float* __restrict__ W2,
             const float* __restrict__ b2,
             const float* __restrict__ W3,
             const float* __restrict__ b3,
             float*       __restrict__ out)
{
    __shared__ __align__(16) float wsm[WFLOATS];       // 10.3 KB
    __shared__ float nsm[BTILE * NPAD];                //  5 KB noise stage
    __shared__ float osm[BTILE * NPAD];                //  5 KB out stage
    __shared__ int   csm[OTILE * KK];

    const int tid   = threadIdx.x;
    const int lane  = tid & 31;
    const int warp  = tid >> 5;
    const int oBase = blockIdx.x * OTILE;
    const int bBlock = blockIdx.y * BTILE;

    // ---- stage noise: 256 b's x 4 o's as scattered float4 loads ----
    {
#pragma unroll
        for (int s = 0; s < 2; s++) {
            int bl = tid + s * 128;
            float4 nv = *(const float4*)(noise + (size_t)(bBlock + bl) * OO + oBase);
            float* d = nsm + bl * NPAD;
            d[0] = nv.x; d[1] = nv.y; d[2] = nv.z; d[3] = nv.w;
        }
    }

    // ---- stage neuron-paired weights (i-major L1) for 4 o's ----
#pragma unroll 1
    for (int idx = tid; idx < WFLOATS; idx += 128) {
        int ol  = idx / WSTRIDE;
        int off = idx - ol * WSTRIDE;
        int o   = oBase + ol;
        float v = 0.0f;
        if (off < 180) {
            int i = off / 20;
            int r = off - i * 20;
            v = W1[o * 180 + i * 20 + r];
        } else if (off < 200) {
            v = b1[o * 20 + (off - 180)];
        } else if (off < 600) {
            int t = off - 200;
            int g = t / 20;
            int r = t - g * 20;
            int jp = r >> 1, sub = r & 1;
            v = W2[o * 400 + (2 * jp + sub) * 20 + g];
        } else if (off < 640) {
            int t = off - 600;
            int g = t >> 1;
            v = (t & 1) ? W3[o * 20 + g] : b2[o * 20 + g];
        } else if (off == 640) {
            v = b3[o];
        }
        wsm[idx] = v;
    }
    if (tid < OTILE * KK) csm[tid] = cause[oBase * KK + tid];
    __syncthreads();

    const int o = oBase + warp;
    const float* wbF = wsm + warp * WSTRIDE;
    const int*   cw  = csm + warp * KK;

#pragma unroll 1
    for (int pass = 0; pass < 2; ++pass) {
        const int blLoc = pass * (BTILE / 2) + lane;       // block-local b: blLoc+32q
        const int bb = bBlock + blLoc;                     // global b

        // ---- gather pipeline: gn = prefetch buffer, d = dup'd current ----
        float gn[BPP];
        ull   d[BPP];
#pragma unroll
        for (int q = 0; q < BPP; q++)
            gn[q] = nsm[(blLoc + 32 * q) * NPAD + warp];   // conflict-free (odd stride)

        ull a[BPP][HH / 2];
        {
            // i = 0 (noise): convert, then prefetch cw[0]
#pragma unroll
            for (int q = 0; q < BPP; q++) d[q] = dup2(gn[q]);
            const float* xc = g_xT + (size_t)cw[0] * BB + bb;
#pragma unroll
            for (int q = 0; q < BPP; q++) gn[q] = xc[32 * q];

            const ulonglong2* w0 = (const ulonglong2*)(wbF);        // i=0 block
            const ulonglong2* wb = (const ulonglong2*)(wbF + 180);  // b1 pairs
#pragma unroll
            for (int qd = 0; qd < 5; qd++) {
                ulonglong2 w  = w0[qd];
                ulonglong2 bq = wb[qd];
#pragma unroll
                for (int q = 0; q < BPP; q++) {
                    a[q][2 * qd]     = fma2(d[q], w.x, bq.x);
                    a[q][2 * qd + 1] = fma2(d[q], w.y, bq.y);
                }
            }
        }
#pragma unroll 1
        for (int i = 1; i <= KK; ++i) {
#pragma unroll
            for (int q = 0; q < BPP; q++) d[q] = dup2(gn[q]);
            {
                int cn = cw[(i < KK) ? i : (KK - 1)];   // last prefetch harmless
                const float* xc = g_xT + (size_t)cn * BB + bb;
#pragma unroll
                for (int q = 0; q < BPP; q++) gn[q] = xc[32 * q];
            }
            const ulonglong2* wi = (const ulonglong2*)(wbF + i * 20);
#pragma unroll
            for (int qd = 0; qd < 5; qd++) {
                ulonglong2 w = wi[qd];
#pragma unroll
                for (int q = 0; q < BPP; q++) {
                    a[q][2 * qd]     = fma2(d[q], w.x, a[q][2 * qd]);
                    a[q][2 * qd + 1] = fma2(d[q], w.y, a[q][2 * qd + 1]);
                }
            }
        }
#pragma unroll
        for (int jp = 0; jp < HH / 2; jp++)
#pragma unroll
            for (int q = 0; q < BPP; q++)
                a[q][jp] = tanh2(a[q][jp]);

        float acc[BPP];
        {
            float b3v = wbF[640];
#pragma unroll
            for (int q = 0; q < BPP; q++) acc[q] = b3v;
        }
#pragma unroll 1
        for (int g = 0; g < HH; g++) {
            const ulonglong2* wg = (const ulonglong2*)(wbF + 200 + g * 20);
            ull p[BPP];
#pragma unroll
            for (int q = 0; q < BPP; q++) p[q] = 0ull;
#pragma unroll
            for (int qd = 0; qd < 5; qd++) {
                ulonglong2 w = wg[qd];
#pragma unroll
                for (int q = 0; q < BPP; q++) {
                    p[q] = fma2(a[q][2 * qd],     w.x, p[q]);
                    p[q] = fma2(a[q][2 * qd + 1], w.y, p[q]);
                }
            }
            float2 bw = *(const float2*)(wbF + 600 + 2 * g);   // (b2[g], W3[g])
#pragma unroll
            for (int q = 0; q < BPP; q++) {
                float2 s = unpack2(p[q]);
                acc[q] = fmaf(tanh_f(s.x + s.y + bw.x), bw.y, acc[q]);
            }
        }

        // stage results (conflict-free: odd stride)
#pragma unroll
        for (int q = 0; q < BPP; q++)
            osm[(blLoc + 32 * q) * NPAD + warp] = acc[q];
    }

    __syncthreads();

    // ---- write out: 256 b's x 4 o's as scattered float4 stores ----
#pragma unroll
    for (int s = 0; s < 2; s++) {
        int bl = tid + s * 128;
        const float* sp = osm + bl * NPAD;
        float4 ov = make_float4(sp[0], sp[1], sp[2], sp[3]);
        *(float4*)(out + (size_t)(bBlock + bl) * OO + oBase) = ov;
    }
}

extern "C" void kernel_launch(void* const* d_in, const int* in_sizes, int n_in,
                              void* d_out, int out_size)
{
    const float* x     = (const float*)d_in[0];
    const float* noise = (const float*)d_in[1];
    const int*   cause = (const int*)  d_in[2];
    const float* W1    = (const float*)d_in[3];
    const float* b1    = (const float*)d_in[4];
    const float* W2    = (const float*)d_in[5];
    const float* b2    = (const float*)d_in[6];
    const float* W3    = (const float*)d_in[7];
    const float* b3    = (const float*)d_in[8];
    float* out = (float*)d_out;

    float* xT;
    cudaGetSymbolAddress((void**)&xT, g_xT);

    dim3 tb(32, 8);
    // x [8192,128] -> xT [128,8192]
    transpose_k<<<dim3(LL / 32, BB / 32), tb>>>(x, xT, BB, LL);

    medil_kernel<<<dim3(OO / OTILE, BB / BTILE), 128>>>(noise, cause, W1, b1, W2, b2, W3, b3, out);
}

// round 15
// speedup vs baseline: 1.5939x; 1.5939x over previous
#include <cuda_runtime.h>
#include <cstdint>

typedef unsigned long long ull;

#define BB    8192
#define LL    128
#define OO    512
#define KK    8
#define HH    20

#define OTILE   4      // o's per block, one per warp (128 threads)
#define BTILE   256    // b's per block (2 passes x 4 per thread x 32 lanes)
#define BPP     4      // b's per pass per thread

#define WSTRIDE 644
#define WFLOATS (OTILE * WSTRIDE)
#define NPAD    5      // nsm/osm row stride (floats): odd -> conflict-free column reads

__device__ float g_xT[LL * BB];        //  4 MB : xT[l][b]

static __device__ __forceinline__ ull pack2(float lo, float hi) {
    ull r; asm("mov.b64 %0, {%1, %2};" : "=l"(r) : "f"(lo), "f"(hi)); return r;
}
static __device__ __forceinline__ float2 unpack2(ull v) {
    float2 f; asm("mov.b64 {%0, %1}, %2;" : "=f"(f.x), "=f"(f.y) : "l"(v)); return f;
}
static __device__ __forceinline__ ull dup2(float v) {
    ull r; asm("mov.b64 %0, {%1, %1};" : "=l"(r) : "f"(v)); return r;
}
static __device__ __forceinline__ ull fma2(ull a, ull b, ull c) {
    ull d; asm("fma.rn.f32x2 %0, %1, %2, %3;" : "=l"(d) : "l"(a), "l"(b), "l"(c)); return d;
}
static __device__ __forceinline__ float tanh_f(float x) {
    float r; asm("tanh.approx.f32 %0, %1;" : "=f"(r) : "f"(x)); return r;
}
static __device__ __forceinline__ ull tanh2(ull v) {
    float2 f = unpack2(v);
    return pack2(tanh_f(f.x), tanh_f(f.y));
}

__global__ void __launch_bounds__(256)
transpose_k(const float* __restrict__ src, float* __restrict__ dst,
            int rows, int cols)
{
    __shared__ float tile[32][33];
    int c  = blockIdx.x * 32 + threadIdx.x;
    int r0 = blockIdx.y * 32;
#pragma unroll
    for (int j = 0; j < 32; j += 8)
        tile[threadIdx.y + j][threadIdx.x] =
            src[(size_t)(r0 + threadIdx.y + j) * cols + c];
    __syncthreads();
    int r  = r0 + threadIdx.x;
    int c0 = blockIdx.x * 32 + threadIdx.y;
#pragma unroll
    for (int j = 0; j < 32; j += 8)
        dst[(size_t)(c0 + j) * rows + r] = tile[threadIdx.x][threadIdx.y + j];
}

__global__ void __launch_bounds__(128, 3)
medil_kernel(const float* __restrict__ noise,
             const int*   __restrict__ cause,
             const float* __restrict__ W1,
             const float* __restrict__ b1,
             const float* __restrict__ W2,
             const float* __restrict__ b2,
             const float* __restrict__ W3,
             const float* __restrict__ b3,
             float*       __restrict__ out)
{
    __shared__ __align__(16) float wsm[WFLOATS];       // 10.3 KB
    __shared__ float nsm[BTILE * NPAD];                //  5 KB noise stage
    __shared__ float osm[BTILE * NPAD];                //  5 KB out stage
    __shared__ int   csm[OTILE * KK];

    const int tid   = threadIdx.x;
    const int lane  = tid & 31;
    const int warp  = tid >> 5;
    const int oBase = blockIdx.x * OTILE;
    const int bBlock = blockIdx.y * BTILE;

    // ---- stage noise: 256 b's x 4 o's as scattered float4 loads ----
    {
#pragma unroll
        for (int s = 0; s < 2; s++) {
            int bl = tid + s * 128;
            float4 nv = *(const float4*)(noise + (size_t)(bBlock + bl) * OO + oBase);
            float* d = nsm + bl * NPAD;
            d[0] = nv.x; d[1] = nv.y; d[2] = nv.z; d[3] = nv.w;
        }
    }

    // ---- stage neuron-paired weights (i-major L1) for 4 o's ----
#pragma unroll 1
    for (int idx = tid; idx < WFLOATS; idx += 128) {
        int ol  = idx / WSTRIDE;
        int off = idx - ol * WSTRIDE;
        int o   = oBase + ol;
        float v = 0.0f;
        if (off < 180) {
            int i = off / 20;
            int r = off - i * 20;
            v = W1[o * 180 + i * 20 + r];
        } else if (off < 200) {
            v = b1[o * 20 + (off - 180)];
        } else if (off < 600) {
            int t = off - 200;
            int g = t / 20;
            int r = t - g * 20;
            int jp = r >> 1, sub = r & 1;
            v = W2[o * 400 + (2 * jp + sub) * 20 + g];
        } else if (off < 640) {
            int t = off - 600;
            int g = t >> 1;
            v = (t & 1) ? W3[o * 20 + g] : b2[o * 20 + g];
        } else if (off == 640) {
            v = b3[o];
        }
        wsm[idx] = v;
    }
    if (tid < OTILE * KK) csm[tid] = cause[oBase * KK + tid];
    __syncthreads();

    const int o = oBase + warp;
    const float* wbF = wsm + warp * WSTRIDE;
    const int*   cw  = csm + warp * KK;

#pragma unroll 1
    for (int pass = 0; pass < 2; ++pass) {
        const int blLoc = pass * (BTILE / 2) + lane;       // block-local b: blLoc+32q
        const int bb = bBlock + blLoc;                     // global b

        // ---- gather pipeline: gn = prefetch buffer, d = dup'd current ----
        float gn[BPP];
        ull   d[BPP];
#pragma unroll
        for (int q = 0; q < BPP; q++)
            gn[q] = nsm[(blLoc + 32 * q) * NPAD + warp];   // conflict-free (odd stride)

        ull a[BPP][HH / 2];
        {
            // i = 0 (noise): convert, then prefetch cw[0]
#pragma unroll
            for (int q = 0; q < BPP; q++) d[q] = dup2(gn[q]);
            const float* xc = g_xT + (size_t)cw[0] * BB + bb;
#pragma unroll
            for (int q = 0; q < BPP; q++) gn[q] = xc[32 * q];

            const ulonglong2* w0 = (const ulonglong2*)(wbF);        // i=0 block
            const ulonglong2* wb = (const ulonglong2*)(wbF + 180);  // b1 pairs
#pragma unroll
            for (int qd = 0; qd < 5; qd++) {
                ulonglong2 w  = w0[qd];
                ulonglong2 bq = wb[qd];
#pragma unroll
                for (int q = 0; q < BPP; q++) {
                    a[q][2 * qd]     = fma2(d[q], w.x, bq.x);
                    a[q][2 * qd + 1] = fma2(d[q], w.y, bq.y);
                }
            }
        }
#pragma unroll 1
        for (int i = 1; i <= KK; ++i) {
#pragma unroll
            for (int q = 0; q < BPP; q++) d[q] = dup2(gn[q]);
            {
                int cn = cw[(i < KK) ? i : (KK - 1)];   // last prefetch harmless
                const float* xc = g_xT + (size_t)cn * BB + bb;
#pragma unroll
                for (int q = 0; q < BPP; q++) gn[q] = xc[32 * q];
            }
            const ulonglong2* wi = (const ulonglong2*)(wbF + i * 20);
#pragma unroll
            for (int qd = 0; qd < 5; qd++) {
                ulonglong2 w = wi[qd];
#pragma unroll
                for (int q = 0; q < BPP; q++) {
                    a[q][2 * qd]     = fma2(d[q], w.x, a[q][2 * qd]);
                    a[q][2 * qd + 1] = fma2(d[q], w.y, a[q][2 * qd + 1]);
                }
            }
        }
#pragma unroll
        for (int jp = 0; jp < HH / 2; jp++)
#pragma unroll
            for (int q = 0; q < BPP; q++)
                a[q][jp] = tanh2(a[q][jp]);

        float acc[BPP];
        {
            float b3v = wbF[640];
#pragma unroll
            for (int q = 0; q < BPP; q++) acc[q] = b3v;
        }
#pragma unroll 1
        for (int g = 0; g < HH; g++) {
            const ulonglong2* wg = (const ulonglong2*)(wbF + 200 + g * 20);
            ull p[BPP];
#pragma unroll
            for (int q = 0; q < BPP; q++) p[q] = 0ull;
#pragma unroll
            for (int qd = 0; qd < 5; qd++) {
                ulonglong2 w = wg[qd];
#pragma unroll
                for (int q = 0; q < BPP; q++) {
                    p[q] = fma2(a[q][2 * qd],     w.x, p[q]);
                    p[q] = fma2(a[q][2 * qd + 1], w.y, p[q]);
                }
            }
            float2 bw = *(const float2*)(wbF + 600 + 2 * g);   // (b2[g], W3[g])
#pragma unroll
            for (int q = 0; q < BPP; q++) {
                float2 s = unpack2(p[q]);
                acc[q] = fmaf(tanh_f(s.x + s.y + bw.x), bw.y, acc[q]);
            }
        }

        // stage results (conflict-free: odd stride)
#pragma unroll
        for (int q = 0; q < BPP; q++)
            osm[(blLoc + 32 * q) * NPAD + warp] = acc[q];
    }

    __syncthreads();

    // ---- write out: 256 b's x 4 o's as scattered float4 stores ----
#pragma unroll
    for (int s = 0; s < 2; s++) {
        int bl = tid + s * 128;
        const float* sp = osm + bl * NPAD;
        float4 ov = make_float4(sp[0], sp[1], sp[2], sp[3]);
        *(float4*)(out + (size_t)(bBlock + bl) * OO + oBase) = ov;
    }
}

extern "C" void kernel_launch(void* const* d_in, const int* in_sizes, int n_in,
                              void* d_out, int out_size)
{
    const float* x     = (const float*)d_in[0];
    const float* noise = (const float*)d_in[1];
    const int*   cause = (const int*)  d_in[2];
    const float* W1    = (const float*)d_in[3];
    const float* b1    = (const float*)d_in[4];
    const float* W2    = (const float*)d_in[5];
    const float* b2    = (const float*)d_in[6];
    const float* W3    = (const float*)d_in[7];
    const float* b3    = (const float*)d_in[8];
    float* out = (float*)d_out;

    float* xT;
    cudaGetSymbolAddress((void**)&xT, g_xT);

    dim3 tb(32, 8);
    // x [8192,128] -> xT [128,8192]
    transpose_k<<<dim3(LL / 32, BB / 32), tb>>>(x, xT, BB, LL);

    medil_kernel<<<dim3(OO / OTILE, BB / BTILE), 128>>>(noise, cause, W1, b1, W2, b2, W3, b3, out);
}

// round 16
// speedup vs baseline: 1.9441x; 1.2197x over previous
#include <cuda_runtime.h>
#include <cstdint>

typedef unsigned long long ull;

#define BB    8192
#define LL    128
#define OO    512
#define KK    8
#define HH    20

#define OTILE   4      // o's per block, one per warp (128 threads)
#define BTILE   256    // b's per block (2 passes x 4 per thread x 32 lanes)
#define BPP     4      // b's per pass per thread

// Packed per-o weight layout (floats), stride 648 (16B multiple):
//  [0,180)   : 9 i-blocks of 20: { (W1[i][2jp],W1[i][2jp+1]) jp=0..9 }
//  [180,200) : 10 pairs (b1[2jp],b1[2jp+1])
//  [200,600) : 20 g-blocks of 20: { (W2[2jp][g],W2[2jp+1][g]) jp=0..9 }
//  [600,620) : 10 float2: (b2[2gp], b2[2gp+1])
//  [620,640) : 10 float2: (W3[2gp], W3[2gp+1])
//  [640]     : b3   (+7 pad)
#define WSTRIDE 648
#define WFLOATS (OTILE * WSTRIDE)
#define NPAD    5      // nsm/osm row stride: odd -> conflict-free column reads

__device__ float g_xT[LL * BB];            //  4 MB : xT[l][b]
__device__ float g_wPack[OO * WSTRIDE];    //  1.3 MB packed weights

static __device__ __forceinline__ ull pack2(float lo, float hi) {
    ull r; asm("mov.b64 %0, {%1, %2};" : "=l"(r) : "f"(lo), "f"(hi)); return r;
}
static __device__ __forceinline__ float2 unpack2(ull v) {
    float2 f; asm("mov.b64 {%0, %1}, %2;" : "=f"(f.x), "=f"(f.y) : "l"(v)); return f;
}
static __device__ __forceinline__ ull dup2(float v) {
    ull r; asm("mov.b64 %0, {%1, %1};" : "=l"(r) : "f"(v)); return r;
}
static __device__ __forceinline__ ull fma2(ull a, ull b, ull c) {
    ull d; asm("fma.rn.f32x2 %0, %1, %2, %3;" : "=l"(d) : "l"(a), "l"(b), "l"(c)); return d;
}
static __device__ __forceinline__ ull add2(ull a, ull b) {
    ull d; asm("add.rn.f32x2 %0, %1, %2;" : "=l"(d) : "l"(a), "l"(b)); return d;
}
static __device__ __forceinline__ float tanh_f(float x) {
    float r; asm("tanh.approx.f32 %0, %1;" : "=f"(r) : "f"(x)); return r;
}
static __device__ __forceinline__ ull tanh2(ull v) {
    float2 f = unpack2(v);
    return pack2(tanh_f(f.x), tanh_f(f.y));
}

// ---------- prep: pack weights into g_wPack (runs once per launch) ----------
__global__ void __launch_bounds__(256)
pack_weights_k(const float* __restrict__ W1, const float* __restrict__ b1,
               const float* __restrict__ W2, const float* __restrict__ b2,
               const float* __restrict__ W3, const float* __restrict__ b3)
{
    int idx = blockIdx.x * 256 + threadIdx.x;
    if (idx >= OO * WSTRIDE) return;
    int o   = idx / WSTRIDE;
    int off = idx - o * WSTRIDE;
    float v = 0.0f;
    if (off < 180) {
        int i = off / 20;
        int r = off - i * 20;
        v = W1[o * 180 + i * 20 + r];
    } else if (off < 200) {
        v = b1[o * 20 + (off - 180)];
    } else if (off < 600) {
        int t = off - 200;
        int g = t / 20;
        int r = t - g * 20;
        int jp = r >> 1, sub = r & 1;
        v = W2[o * 400 + (2 * jp + sub) * 20 + g];
    } else if (off < 620) {
        v = b2[o * 20 + (off - 600)];
    } else if (off < 640) {
        v = W3[o * 20 + (off - 620)];
    } else if (off == 640) {
        v = b3[o];
    }
    g_wPack[idx] = v;
}

__global__ void __launch_bounds__(256)
transpose_k(const float* __restrict__ src, float* __restrict__ dst,
            int rows, int cols)
{
    __shared__ float tile[32][33];
    int c  = blockIdx.x * 32 + threadIdx.x;
    int r0 = blockIdx.y * 32;
#pragma unroll
    for (int j = 0; j < 32; j += 8)
        tile[threadIdx.y + j][threadIdx.x] =
            src[(size_t)(r0 + threadIdx.y + j) * cols + c];
    __syncthreads();
    int r  = r0 + threadIdx.x;
    int c0 = blockIdx.x * 32 + threadIdx.y;
#pragma unroll
    for (int j = 0; j < 32; j += 8)
        dst[(size_t)(c0 + j) * rows + r] = tile[threadIdx.x][threadIdx.y + j];
}

__global__ void __launch_bounds__(128, 3)
medil_kernel(const float* __restrict__ noise,
             const int*   __restrict__ cause,
             float*       __restrict__ out)
{
    __shared__ __align__(16) float wsm[WFLOATS];       // 10.4 KB
    __shared__ float nsm[BTILE * NPAD];                //  5 KB noise stage
    __shared__ float osm[BTILE * NPAD];                //  5 KB out stage
    __shared__ int   csm[OTILE * KK];

    const int tid   = threadIdx.x;
    const int lane  = tid & 31;
    const int warp  = tid >> 5;
    const int oBase = blockIdx.x * OTILE;
    const int bBlock = blockIdx.y * BTILE;

    // ---- stage noise: 256 b's x 4 o's as scattered float4 loads ----
#pragma unroll
    for (int s = 0; s < 2; s++) {
        int bl = tid + s * 128;
        float4 nv = *(const float4*)(noise + (size_t)(bBlock + bl) * OO + oBase);
        float* d = nsm + bl * NPAD;
        d[0] = nv.x; d[1] = nv.y; d[2] = nv.z; d[3] = nv.w;
    }

    // ---- stage packed weights: coalesced float4 copy (648*4 floats = 648 f4) ----
    {
        const float4* src = (const float4*)(g_wPack + (size_t)oBase * WSTRIDE);
        float4* dst = (float4*)wsm;
#pragma unroll
        for (int s = 0; s < 6; s++) {
            int i4 = tid + s * 128;
            if (i4 < WFLOATS / 4) dst[i4] = src[i4];
        }
    }
    if (tid < OTILE * KK) csm[tid] = cause[oBase * KK + tid];
    __syncthreads();

    const float* wbF = wsm + warp * WSTRIDE;
    const int*   cw  = csm + warp * KK;

#pragma unroll 1
    for (int pass = 0; pass < 2; ++pass) {
        const int blLoc = pass * (BTILE / 2) + lane;       // block-local b: blLoc+32q
        const int bb = bBlock + blLoc;                     // global b

        float gn[BPP];
        ull   d[BPP];
#pragma unroll
        for (int q = 0; q < BPP; q++)
            gn[q] = nsm[(blLoc + 32 * q) * NPAD + warp];   // conflict-free

        ull a[BPP][HH / 2];
        {
#pragma unroll
            for (int q = 0; q < BPP; q++) d[q] = dup2(gn[q]);
            const float* xc = g_xT + (size_t)cw[0] * BB + bb;
#pragma unroll
            for (int q = 0; q < BPP; q++) gn[q] = xc[32 * q];

            const ulonglong2* w0 = (const ulonglong2*)(wbF);        // i=0
            const ulonglong2* wb = (const ulonglong2*)(wbF + 180);  // b1 pairs
#pragma unroll
            for (int qd = 0; qd < 5; qd++) {
                ulonglong2 w  = w0[qd];
                ulonglong2 bq = wb[qd];
#pragma unroll
                for (int q = 0; q < BPP; q++) {
                    a[q][2 * qd]     = fma2(d[q], w.x, bq.x);
                    a[q][2 * qd + 1] = fma2(d[q], w.y, bq.y);
                }
            }
        }
#pragma unroll 1
        for (int i = 1; i <= KK; ++i) {
#pragma unroll
            for (int q = 0; q < BPP; q++) d[q] = dup2(gn[q]);
            {
                int cn = cw[(i < KK) ? i : (KK - 1)];
                const float* xc = g_xT + (size_t)cn * BB + bb;
#pragma unroll
                for (int q = 0; q < BPP; q++) gn[q] = xc[32 * q];
            }
            const ulonglong2* wi = (const ulonglong2*)(wbF + i * 20);
#pragma unroll
            for (int qd = 0; qd < 5; qd++) {
                ulonglong2 w = wi[qd];
#pragma unroll
                for (int q = 0; q < BPP; q++) {
                    a[q][2 * qd]     = fma2(d[q], w.x, a[q][2 * qd]);
                    a[q][2 * qd + 1] = fma2(d[q], w.y, a[q][2 * qd + 1]);
                }
            }
        }
#pragma unroll
        for (int jp = 0; jp < HH / 2; jp++)
#pragma unroll
            for (int q = 0; q < BPP; q++)
                a[q][jp] = tanh2(a[q][jp]);

        // ---- layers 2+3, g-PAIRED epilogue: two g's per tanh2/fma2 ----
        ull acc[BPP];
        {
            ull z = dup2(wbF[640] * 0.5f);   // b3/2 in each lane; lanes summed at end
#pragma unroll
            for (int q = 0; q < BPP; q++) acc[q] = z;
        }
#pragma unroll 2
        for (int gp = 0; gp < HH / 2; gp++) {
            const ulonglong2* wgA = (const ulonglong2*)(wbF + 200 + (2 * gp)     * 20);
            const ulonglong2* wgB = (const ulonglong2*)(wbF + 200 + (2 * gp + 1) * 20);
            ull pA[BPP], pB[BPP];
#pragma unroll
            for (int q = 0; q < BPP; q++) { pA[q] = 0ull; pB[q] = 0ull; }
#pragma unroll
            for (int qd = 0; qd < 5; qd++) {
                ulonglong2 wA = wgA[qd];
                ulonglong2 wB = wgB[qd];
#pragma unroll
                for (int q = 0; q < BPP; q++) {
                    pA[q] = fma2(a[q][2 * qd],     wA.x, pA[q]);
                    pB[q] = fma2(a[q][2 * qd],     wB.x, pB[q]);
                    pA[q] = fma2(a[q][2 * qd + 1], wA.y, pA[q]);
                    pB[q] = fma2(a[q][2 * qd + 1], wB.y, pB[q]);
                }
            }
            ull b2p = *(const ull*)(wbF + 600 + 2 * gp);   // (b2[2gp], b2[2gp+1])
            ull w3p = *(const ull*)(wbF + 620 + 2 * gp);   // (W3[2gp], W3[2gp+1])
#pragma unroll
            for (int q = 0; q < BPP; q++) {
                float2 sA = unpack2(pA[q]);
                float2 sB = unpack2(pB[q]);
                ull s = add2(pack2(sA.x + sA.y, sB.x + sB.y), b2p);
                acc[q] = fma2(tanh2(s), w3p, acc[q]);
            }
        }

        // stage results (lanes of acc sum to the output)
#pragma unroll
        for (int q = 0; q < BPP; q++) {
            float2 r = unpack2(acc[q]);
            osm[(blLoc + 32 * q) * NPAD + warp] = r.x + r.y;
        }
    }

    __syncthreads();

    // ---- write out: 256 b's x 4 o's as scattered float4 stores ----
#pragma unroll
    for (int s = 0; s < 2; s++) {
        int bl = tid + s * 128;
        const float* sp = osm + bl * NPAD;
        float4 ov = make_float4(sp[0], sp[1], sp[2], sp[3]);
        *(float4*)(out + (size_t)(bBlock + bl) * OO + oBase) = ov;
    }
}

extern "C" void kernel_launch(void* const* d_in, const int* in_sizes, int n_in,
                              void* d_out, int out_size)
{
    const float* x     = (const float*)d_in[0];
    const float* noise = (const float*)d_in[1];
    const int*   cause = (const int*)  d_in[2];
    const float* W1    = (const float*)d_in[3];
    const float* b1    = (const float*)d_in[4];
    const float* W2    = (const float*)d_in[5];
    const float* b2    = (const float*)d_in[6];
    const float* W3    = (const float*)d_in[7];
    const float* b3    = (const float*)d_in[8];
    float* out = (float*)d_out;

    float* xT;
    cudaGetSymbolAddress((void**)&xT, g_xT);

    dim3 tb(32, 8);
    transpose_k<<<dim3(LL / 32, BB / 32), tb>>>(x, xT, BB, LL);
    pack_weights_k<<<(OO * WSTRIDE + 255) / 256, 256>>>(W1, b1, W2, b2, W3, b3);

    medil_kernel<<<dim3(OO / OTILE, BB / BTILE), 128>>>(noise, cause, out);
}

// round 17
// speedup vs baseline: 1.9544x; 1.0053x over previous
#include <cuda_runtime.h>
#include <cstdint>

typedef unsigned long long ull;

#define BB    8192
#define LL    128
#define OO    512
#define KK    8
#define HH    20

#define OTILE   4      // o's per block, one per warp (128 threads)
#define BTILE   256    // b's per block (2 passes x 4 per thread x 32 lanes)
#define BPP     4      // b's per pass per thread

// Packed per-o weight layout (floats), stride 648 (16B multiple):
//  [0,180)   : 9 i-blocks of 20: { (W1[i][2jp],W1[i][2jp+1]) jp=0..9 }
//  [180,200) : 10 pairs (b1[2jp],b1[2jp+1])
//  [200,600) : 20 g-blocks of 20: { (W2[2jp][g],W2[2jp+1][g]) jp=0..9 }
//  [600,620) : 10 float2: (b2[2gp], b2[2gp+1])
//  [620,640) : 10 float2: (W3[2gp], W3[2gp+1])
//  [640]     : b3   (+7 pad)
#define WSTRIDE 648
#define WFLOATS (OTILE * WSTRIDE)
#define NPAD    5      // nsm/osm row stride: odd -> conflict-free column reads

__device__ float g_xT[LL * BB];            //  4 MB : xT[l][b]
__device__ float g_wPack[OO * WSTRIDE];    //  1.3 MB packed weights

static __device__ __forceinline__ ull pack2(float lo, float hi) {
    ull r; asm("mov.b64 %0, {%1, %2};" : "=l"(r) : "f"(lo), "f"(hi)); return r;
}
static __device__ __forceinline__ float2 unpack2(ull v) {
    float2 f; asm("mov.b64 {%0, %1}, %2;" : "=f"(f.x), "=f"(f.y) : "l"(v)); return f;
}
static __device__ __forceinline__ ull dup2(float v) {
    ull r; asm("mov.b64 %0, {%1, %1};" : "=l"(r) : "f"(v)); return r;
}
static __device__ __forceinline__ ull fma2(ull a, ull b, ull c) {
    ull d; asm("fma.rn.f32x2 %0, %1, %2, %3;" : "=l"(d) : "l"(a), "l"(b), "l"(c)); return d;
}
static __device__ __forceinline__ ull add2(ull a, ull b) {
    ull d; asm("add.rn.f32x2 %0, %1, %2;" : "=l"(d) : "l"(a), "l"(b)); return d;
}
static __device__ __forceinline__ float tanh_f(float x) {
    float r; asm("tanh.approx.f32 %0, %1;" : "=f"(r) : "f"(x)); return r;
}
static __device__ __forceinline__ ull tanh2(ull v) {
    float2 f = unpack2(v);
    return pack2(tanh_f(f.x), tanh_f(f.y));
}

// ---------- prep: pack weights into g_wPack ----------
__global__ void __launch_bounds__(256)
pack_weights_k(const float* __restrict__ W1, const float* __restrict__ b1,
               const float* __restrict__ W2, const float* __restrict__ b2,
               const float* __restrict__ W3, const float* __restrict__ b3)
{
    int idx = blockIdx.x * 256 + threadIdx.x;
    if (idx >= OO * WSTRIDE) return;
    int o   = idx / WSTRIDE;
    int off = idx - o * WSTRIDE;
    float v = 0.0f;
    if (off < 180) {
        int i = off / 20;
        int r = off - i * 20;
        v = W1[o * 180 + i * 20 + r];
    } else if (off < 200) {
        v = b1[o * 20 + (off - 180)];
    } else if (off < 600) {
        int t = off - 200;
        int g = t / 20;
        int r = t - g * 20;
        int jp = r >> 1, sub = r & 1;
        v = W2[o * 400 + (2 * jp + sub) * 20 + g];
    } else if (off < 620) {
        v = b2[o * 20 + (off - 600)];
    } else if (off < 640) {
        v = W3[o * 20 + (off - 620)];
    } else if (off == 640) {
        v = b3[o];
    }
    g_wPack[idx] = v;
}

__global__ void __launch_bounds__(256)
transpose_k(const float* __restrict__ src, float* __restrict__ dst,
            int rows, int cols)
{
    __shared__ float tile[32][33];
    int c  = blockIdx.x * 32 + threadIdx.x;
    int r0 = blockIdx.y * 32;
#pragma unroll
    for (int j = 0; j < 32; j += 8)
        tile[threadIdx.y + j][threadIdx.x] =
            src[(size_t)(r0 + threadIdx.y + j) * cols + c];
    __syncthreads();
    int r  = r0 + threadIdx.x;
    int c0 = blockIdx.x * 32 + threadIdx.y;
#pragma unroll
    for (int j = 0; j < 32; j += 8)
        dst[(size_t)(c0 + j) * rows + r] = tile[threadIdx.x][threadIdx.y + j];
}

__global__ void __launch_bounds__(128, 3)
medil_kernel(const float* __restrict__ noise,
             const int*   __restrict__ cause,
             float*       __restrict__ out)
{
    __shared__ __align__(16) float wsm[WFLOATS];       // 10.4 KB
    __shared__ float nsm[BTILE * NPAD];                //  5 KB noise stage
    __shared__ float osm[BTILE * NPAD];                //  5 KB out stage
    __shared__ int   csm[OTILE * KK];

    const int tid   = threadIdx.x;
    const int lane  = tid & 31;
    const int warp  = tid >> 5;
    const int oBase = blockIdx.x * OTILE;
    const int bBlock = blockIdx.y * BTILE;

    // ---- stage noise: 256 b's x 4 o's as scattered float4 loads ----
#pragma unroll
    for (int s = 0; s < 2; s++) {
        int bl = tid + s * 128;
        float4 nv = *(const float4*)(noise + (size_t)(bBlock + bl) * OO + oBase);
        float* d = nsm + bl * NPAD;
        d[0] = nv.x; d[1] = nv.y; d[2] = nv.z; d[3] = nv.w;
    }

    // ---- stage packed weights: coalesced float4 copy ----
    {
        const float4* src = (const float4*)(g_wPack + (size_t)oBase * WSTRIDE);
        float4* dst = (float4*)wsm;
#pragma unroll
        for (int s = 0; s < 6; s++) {
            int i4 = tid + s * 128;
            if (i4 < WFLOATS / 4) dst[i4] = src[i4];
        }
    }
    if (tid < OTILE * KK) csm[tid] = cause[oBase * KK + tid];
    __syncthreads();

    const float* wbF = wsm + warp * WSTRIDE;
    const int*   cw  = csm + warp * KK;

#pragma unroll 1
    for (int pass = 0; pass < 2; ++pass) {
        const int blLoc = pass * (BTILE / 2) + lane;       // block-local b
        const int bb = bBlock + blLoc;                     // global b

        // ---- gather pipeline, distance 2: g1 = next, g2 = next-next ----
        float g1[BPP], g2[BPP];
        ull   d[BPP];
        float cur[BPP];
#pragma unroll
        for (int q = 0; q < BPP; q++)
            cur[q] = nsm[(blLoc + 32 * q) * NPAD + warp];  // i=0 input (noise)
        {
            const float* xc0 = g_xT + (size_t)cw[0] * BB + bb;
            const float* xc1 = g_xT + (size_t)cw[1] * BB + bb;
#pragma unroll
            for (int q = 0; q < BPP; q++) g1[q] = xc0[32 * q];
#pragma unroll
            for (int q = 0; q < BPP; q++) g2[q] = xc1[32 * q];
        }

        ull a[BPP][HH / 2];
        {
#pragma unroll
            for (int q = 0; q < BPP; q++) d[q] = dup2(cur[q]);
            const ulonglong2* w0 = (const ulonglong2*)(wbF);        // i=0
            const ulonglong2* wb = (const ulonglong2*)(wbF + 180);  // b1 pairs
#pragma unroll
            for (int qd = 0; qd < 5; qd++) {
                ulonglong2 w  = w0[qd];
                ulonglong2 bq = wb[qd];
#pragma unroll
                for (int q = 0; q < BPP; q++) {
                    a[q][2 * qd]     = fma2(d[q], w.x, bq.x);
                    a[q][2 * qd + 1] = fma2(d[q], w.y, bq.y);
                }
            }
        }
#pragma unroll 2
        for (int i = 1; i <= KK; ++i) {
#pragma unroll
            for (int q = 0; q < BPP; q++) d[q] = dup2(g1[q]);
#pragma unroll
            for (int q = 0; q < BPP; q++) g1[q] = g2[q];
            {
                int cn = cw[(i + 1 < KK) ? (i + 1) : (KK - 1)];  // prefetch i+2 (clamped)
                const float* xc = g_xT + (size_t)cn * BB + bb;
#pragma unroll
                for (int q = 0; q < BPP; q++) g2[q] = xc[32 * q];
            }
            const ulonglong2* wi = (const ulonglong2*)(wbF + i * 20);
#pragma unroll
            for (int qd = 0; qd < 5; qd++) {
                ulonglong2 w = wi[qd];
#pragma unroll
                for (int q = 0; q < BPP; q++) {
                    a[q][2 * qd]     = fma2(d[q], w.x, a[q][2 * qd]);
                    a[q][2 * qd + 1] = fma2(d[q], w.y, a[q][2 * qd + 1]);
                }
            }
        }
#pragma unroll
        for (int jp = 0; jp < HH / 2; jp++)
#pragma unroll
            for (int q = 0; q < BPP; q++)
                a[q][jp] = tanh2(a[q][jp]);

        // ---- layers 2+3, g-PAIRED epilogue ----
        ull acc[BPP];
        {
            ull z = dup2(wbF[640] * 0.5f);   // b3/2 per lane; lanes summed at end
#pragma unroll
            for (int q = 0; q < BPP; q++) acc[q] = z;
        }
#pragma unroll 2
        for (int gp = 0; gp < HH / 2; gp++) {
            const ulonglong2* wgA = (const ulonglong2*)(wbF + 200 + (2 * gp)     * 20);
            const ulonglong2* wgB = (const ulonglong2*)(wbF + 200 + (2 * gp + 1) * 20);
            ull pA[BPP], pB[BPP];
#pragma unroll
            for (int q = 0; q < BPP; q++) { pA[q] = 0ull; pB[q] = 0ull; }
#pragma unroll
            for (int qd = 0; qd < 5; qd++) {
                ulonglong2 wA = wgA[qd];
                ulonglong2 wB = wgB[qd];
#pragma unroll
                for (int q = 0; q < BPP; q++) {
                    pA[q] = fma2(a[q][2 * qd],     wA.x, pA[q]);
                    pB[q] = fma2(a[q][2 * qd],     wB.x, pB[q]);
                    pA[q] = fma2(a[q][2 * qd + 1], wA.y, pA[q]);
                    pB[q] = fma2(a[q][2 * qd + 1], wB.y, pB[q]);
                }
            }
            ull b2p = *(const ull*)(wbF + 600 + 2 * gp);   // (b2[2gp], b2[2gp+1])
            ull w3p = *(const ull*)(wbF + 620 + 2 * gp);   // (W3[2gp], W3[2gp+1])
#pragma unroll
            for (int q = 0; q < BPP; q++) {
                float2 sA = unpack2(pA[q]);
                float2 sB = unpack2(pB[q]);
                ull s = add2(pack2(sA.x + sA.y, sB.x + sB.y), b2p);
                acc[q] = fma2(tanh2(s), w3p, acc[q]);
            }
        }

        // stage results (lanes of acc sum to the output)
#pragma unroll
        for (int q = 0; q < BPP; q++) {
            float2 r = unpack2(acc[q]);
            osm[(blLoc + 32 * q) * NPAD + warp] = r.x + r.y;
        }
    }

    __syncthreads();

    // ---- write out: 256 b's x 4 o's as scattered float4 stores ----
#pragma unroll
    for (int s = 0; s < 2; s++) {
        int bl = tid + s * 128;
        const float* sp = osm + bl * NPAD;
        float4 ov = make_float4(sp[0], sp[1], sp[2], sp[3]);
        *(float4*)(out + (size_t)(bBlock + bl) * OO + oBase) = ov;
    }
}

extern "C" void kernel_launch(void* const* d_in, const int* in_sizes, int n_in,
                              void* d_out, int out_size)
{
    const float* x     = (const float*)d_in[0];
    const float* noise = (const float*)d_in[1];
    const int*   cause = (const int*)  d_in[2];
    const float* W1    = (const float*)d_in[3];
    const float* b1    = (const float*)d_in[4];
    const float* W2    = (const float*)d_in[5];
    const float* b2    = (const float*)d_in[6];
    const float* W3    = (const float*)d_in[7];
    const float* b3    = (const float*)d_in[8];
    float* out = (float*)d_out;

    float* xT;
    cudaGetSymbolAddress((void**)&xT, g_xT);

    dim3 tb(32, 8);
    transpose_k<<<dim3(LL / 32, BB / 32), tb>>>(x, xT, BB, LL);
    pack_weights_k<<<(OO * WSTRIDE + 255) / 256, 256>>>(W1, b1, W2, b2, W3, b3);

    medil_kernel<<<dim3(OO / OTILE, BB / BTILE), 128>>>(noise, cause, out);
}